// round 15
// baseline (speedup 1.0000x reference)
#include <cuda_runtime.h>
#include <cuda_fp16.h>
#include <math.h>
#include <stdint.h>

#define BB 64
#define TT 512
#define DD 1024
#define HH 1024
#define VV 128
#define NCTA 128
#define NTHR 512
#define KC 64            // k elements per chunk
#define NCHG 16          // chunks per group per phase (each group owns K/2 = 1024)
#define PB 144           // bytes per staged row (64 fp16 + 8 pad)

// ---- dynamic smem layout (byte offsets) ----
#define ARR    9216            // one staged array: 64 rows * 144B
#define CHUNK  (2 * ARR)       // A(act), W = 18432B per chunk
#define GRING  (4 * CHUNK)     // per-group ring: 4 slots = 73728B
#define SGATE  (2 * GRING)     // 147456: two f32 [64][68] gate buffers (dedicated)
#define GATEB  17408           // one gate buffer
#define SCST   (SGATE + 2 * GATEB)   // 182272: f32 [64][17] persistent c-state
#define STOKS  (SCST + 64 * 17 * 4)  // 186624: two 256B token buffers (parity)
#define SMEM_DYN (STOKS + 512 + 256) // 187392

// ---- persistent device scratch ----
__device__ __half g_WF[2ull * 64 * 64 * 2048];   // permuted weights (fp16)
__device__ __half g_embf[VV * DD];
__device__ __half g_h0f[2][BB][HH];
__device__ __half g_h1f[2][BB][HH];
__device__ float g_Hout[(size_t)BB * TT * HH];
__device__ volatile unsigned g_gen;
__device__ unsigned g_count;

__device__ __forceinline__ float sigf(float v) { return 1.0f / (1.0f + expf(-v)); }

__device__ __forceinline__ uint32_t smem_u32(const void* p) {
    uint32_t a;
    asm("{ .reg .u64 t; cvta.to.shared.u64 t, %1; cvt.u32.u64 %0, t; }" : "=r"(a) : "l"(p));
    return a;
}
__device__ __forceinline__ void cp16(uint32_t dst, const void* src) {
    asm volatile("cp.async.cg.shared.global [%0], [%1], 16;" :: "r"(dst), "l"(src));
}
__device__ __forceinline__ void cp_commit() { asm volatile("cp.async.commit_group;"); }
template<int N> __device__ __forceinline__ void cp_wait() {
    asm volatile("cp.async.wait_group %0;" :: "n"(N));
}
__device__ __forceinline__ void bar_grp(int id) {
    asm volatile("bar.sync %0, 256;" :: "r"(id) : "memory");
}
__device__ __forceinline__ uint32_t lds_u32(uint32_t a) {
    uint32_t v; asm volatile("ld.shared.b32 %0, [%1];" : "=r"(v) : "r"(a)); return v;
}
__device__ __forceinline__ float lds_f32(uint32_t a) {
    float v; asm volatile("ld.shared.f32 %0, [%1];" : "=f"(v) : "r"(a)); return v;
}
__device__ __forceinline__ void sts_u32(uint32_t a, uint32_t v) {
    asm volatile("st.shared.b32 [%0], %1;" :: "r"(a), "r"(v));
}
__device__ __forceinline__ void sts_f32(uint32_t a, float v) {
    asm volatile("st.shared.f32 [%0], %1;" :: "r"(a), "f"(v));
}
__device__ __forceinline__ void sts_v2(uint32_t a, float x, float y) {
    asm volatile("st.shared.v2.f32 [%0], {%1, %2};" :: "r"(a), "f"(x), "f"(y));
}
#define LDSM4(r0, r1, r2, r3, addr) \
    asm volatile("ldmatrix.sync.aligned.m8n8.x4.shared.b16 {%0,%1,%2,%3}, [%4];" \
                 : "=r"(r0), "=r"(r1), "=r"(r2), "=r"(r3) : "r"(addr))

__device__ __forceinline__ void mma_f16(float* d,
    uint32_t a0, uint32_t a1, uint32_t a2, uint32_t a3, uint32_t b0, uint32_t b1) {
    asm volatile("mma.sync.aligned.m16n8k16.row.col.f32.f16.f16.f32 "
                 "{%0,%1,%2,%3}, {%4,%5,%6,%7}, {%8,%9}, {%0,%1,%2,%3};"
                 : "+f"(d[0]), "+f"(d[1]), "+f"(d[2]), "+f"(d[3])
                 : "r"(a0), "r"(a1), "r"(a2), "r"(a3), "r"(b0), "r"(b1));
}

__global__ void init_kernel() {
    int i = blockIdx.x * blockDim.x + threadIdx.x;
    if (i < 2 * BB * HH) {
        ((__half*)g_h0f)[i] = __float2half(0.0f);
        ((__half*)g_h1f)[i] = __float2half(0.0f);
    }
    if (i == 0) { g_count = 0; g_gen = 0; }
}

// weight preconvert: permuted [u][tile][n][k], n = gate*16+j, k over [Wx|Wh]
__global__ void convert_weights_kernel(const float* __restrict__ Wx,
                                       const float* __restrict__ Wh) {
    size_t idx = (size_t)blockIdx.x * blockDim.x + threadIdx.x;
    if (idx >= 2ull * 64 * 64 * 2048) return;
    int k    = idx & 2047;
    int n    = (idx >> 11) & 63;
    int tile = (idx >> 17) & 63;
    int u    = (int)(idx >> 23);
    int gate = n >> 4, j = n & 15;
    int r = gate * 1024 + tile * 16 + j;
    float w = (k < 1024) ? Wx[((size_t)u * 4096 + r) * 1024 + k]
                         : Wh[((size_t)u * 4096 + r) * 1024 + (k - 1024)];
    g_WF[idx] = __float2half(w);
}

__global__ void convert_embed_kernel(const float* __restrict__ embed) {
    int i = blockIdx.x * blockDim.x + threadIdx.x;
    if (i >= VV * DD) return;
    g_embf[i] = __float2half(embed[i]);
}

__device__ __forceinline__ void grid_barrier() {
    __syncthreads();
    if (threadIdx.x == 0) {
        unsigned gen = g_gen;
        __threadfence();
        if (atomicAdd(&g_count, 1u) == NCTA - 1) {
            g_count = 0;
            __threadfence();
            g_gen = gen + 1;
        } else {
            while (g_gen == gen) { __nanosleep(32); }
            __threadfence();
        }
    }
    __syncthreads();
}

// Persistent single-pass fp16 mma.sync LSTM, decoupled dual warp-groups,
// role-split staging (A vs W threads) with cross-phase W prestage and
// dedicated dual gate buffers (no reduction pass, 1 full sync per phase).
// 128 CTAs x 512 thr. CTA: layer u = blockIdx>>6, tile = blockIdx&63.
// Group g owns K half [g*1024, (g+1)*1024); warp tile m32n16 over 64x64.
__global__ __launch_bounds__(NTHR, 1) void lstm_persistent_kernel(
    const int* __restrict__ x, const float* __restrict__ bias)
{
    extern __shared__ char sm_raw[];
    const uint32_t sb = smem_u32(sm_raw);

    const int tid  = threadIdx.x;
    const int wid  = tid >> 5;
    const int lane = tid & 31;
    const int u    = blockIdx.x >> 6;
    const int tile = blockIdx.x & 63;
    const int col0 = tile * 16;

    const int grp = tid >> 8;         // warp-group (k half)
    const int gt  = tid & 255;        // thread within group
    const int w8  = wid & 7;          // warp within group
    const int m0  = (w8 & 1) * 32;
    const int n0  = (w8 >> 1) * 16;
    const int lg  = lane >> 2;
    const int t2  = (lane & 3) * 2;
    const int bar_id = 1 + grp;
    const bool isA = (gt < 128);      // staging role: A (acts) vs W (weights)
    const int st   = gt & 127;        // thread index within staging role

    // ldmatrix lane addresses (byte offsets within a staged array)
    const uint32_t a_lrow = (uint32_t)(m0 + (lane & 7) + ((lane >> 3) & 1) * 8) * PB
                          + ((lane >> 4) & 1) * 16;
    const uint32_t b_lrow = (uint32_t)(n0 + (lane & 7) + ((lane >> 4) & 1) * 8) * PB
                          + ((lane >> 3) & 1) * 16;

    // pointwise role
    const int pj  = tid & 15;
    const int pb0 = tid >> 4;        // 0..31
    const float* bL = bias + u * 4096;
    const float bi_ = bL[0    + col0 + pj];
    const float bf_ = bL[1024 + col0 + pj];
    const float bg_ = bL[2048 + col0 + pj];
    const float bo_ = bL[3072 + col0 + pj];

    for (int i = tid; i < 64 * 17; i += NTHR) sts_f32(sb + SCST + i * 4, 0.0f);
    if (tid < BB) sts_u32(sb + STOKS + tid * 4, (uint32_t)x[tid * TT]);  // tokens t=0
    __syncthreads();

    // group g's weight half starts at k = g*1024
    const __half* wfg = g_WF + ((size_t)(u * 64 + tile) * 64) * 2048 + grp * 1024;
    const uint32_t ringb = sb + (uint32_t)grp * GRING;
    const uint32_t gateb = sb + SGATE + (uint32_t)grp * GATEB;

    // ---- staging lambdas (role-split; 4 cp16 + 1 commit per chunk per thread) ----
    int cur_rbuf = 1, cur_wbuf = 0, cur_tokoff = 0;   // set per phase below
    auto stage_A = [&](int ci) {
#pragma unroll
        for (int i = 0; i < 4; i++) {
            const int slot = st + 128 * i;        // 0..511
            const int row  = slot >> 3;
            const int f4   = slot & 7;
            const uint32_t dst = ringb + (uint32_t)(ci & 3) * CHUNK
                               + (uint32_t)row * PB + f4 * 16;
            const __half* src;
            if (u == 0) {
                if (grp == 0) {
                    int tok = (int)lds_u32(sb + STOKS + cur_tokoff + row * 4);
                    src = g_embf + (size_t)tok * DD + ci * KC + f4 * 8;
                } else {
                    src = g_h0f[cur_rbuf][row] + ci * KC + f4 * 8;
                }
            } else {
                if (grp == 0) src = g_h0f[cur_wbuf][row] + ci * KC + f4 * 8;
                else          src = g_h1f[cur_rbuf][row] + ci * KC + f4 * 8;
            }
            cp16(dst, src);
        }
        cp_commit();
    };
    auto stage_W = [&](int ci) {
#pragma unroll
        for (int i = 0; i < 4; i++) {
            const int slot = st + 128 * i;
            const int row  = slot >> 3;
            const int f4   = slot & 7;
            const uint32_t dst = ringb + (uint32_t)(ci & 3) * CHUNK + ARR
                               + (uint32_t)row * PB + f4 * 16;
            cp16(dst, wfg + (size_t)row * 2048 + ci * KC + f4 * 8);
        }
        cp_commit();
    };

    // initial W prologue (weights are phase-invariant)
    if (!isA) { stage_W(0); stage_W(1); stage_W(2); }

    for (int p = 0; p <= TT; p++) {
        const bool valid = (u == 0) ? (p < TT) : (p >= 1);
        const int  tc    = (u == 0) ? (valid ? p : TT - 1) : (valid ? p - 1 : 0);
        cur_wbuf   = tc & 1;
        cur_rbuf   = (tc + 1) & 1;
        cur_tokoff = (p & 1) * 256;

        // preload tokens for phase p+1 into the other parity buffer (x is static)
        if (tid < BB && p + 1 < TT)
            sts_u32(sb + STOKS + ((p + 1) & 1) * 256 + tid * 4,
                    (uint32_t)x[tid * TT + (p + 1)]);

        // A prologue for this phase (W already prestaged)
        if (isA) { stage_A(0); stage_A(1); stage_A(2); }

        float acc[2][2][4];
#pragma unroll
        for (int a = 0; a < 2; a++)
#pragma unroll
            for (int b = 0; b < 2; b++)
#pragma unroll
                for (int e = 0; e < 4; e++) acc[a][b][e] = 0.0f;

        for (int ci = 0; ci < NCHG; ci++) {
            if (ci < NCHG - 2)       cp_wait<2>();
            else if (ci == NCHG - 2) cp_wait<1>();
            else                     cp_wait<0>();
            bar_grp(bar_id);                      // chunk ci ready; compute(ci-1) done
            if (ci + 3 < NCHG) { if (isA) stage_A(ci + 3); else stage_W(ci + 3); }
            else if (ci == NCHG - 1 && !isA && p < TT) {
                // prestage next phase's W into slots 0,1,2 (free: computes 12-14 done)
                stage_W(0); stage_W(1); stage_W(2);
            }

            const uint32_t cb = ringb + (uint32_t)(ci & 3) * CHUNK;
            const uint32_t aA = cb + a_lrow;
            const uint32_t bW = cb + ARR + b_lrow;
#pragma unroll
            for (int ks = 0; ks < 4; ks++) {
                const uint32_t ko = ks * 32;
                uint32_t a[8], b[4];
                LDSM4(a[0], a[1], a[2], a[3], aA + ko);
                LDSM4(a[4], a[5], a[6], a[7], aA + ko + 16 * PB);
                LDSM4(b[0], b[1], b[2], b[3], bW + ko);
#pragma unroll
                for (int mi = 0; mi < 2; mi++) {
                    const uint32_t* A = a + mi * 4;
#pragma unroll
                    for (int ni = 0; ni < 2; ni++)
                        mma_f16(acc[mi][ni], A[0], A[1], A[2], A[3], b[2 * ni], b[2 * ni + 1]);
                }
            }
        }

        // each warp writes its exclusive gate region in ITS GROUP's buffer: no bar needed
#pragma unroll
        for (int mi = 0; mi < 2; mi++) {
            const uint32_t grow = gateb + (uint32_t)(m0 + mi * 16 + lg) * 272
                                + (uint32_t)(n0 + t2) * 4;
#pragma unroll
            for (int ni = 0; ni < 2; ni++) {
                sts_v2(grow + ni * 32,           acc[mi][ni][0], acc[mi][ni][1]);
                sts_v2(grow + ni * 32 + 8 * 272, acc[mi][ni][2], acc[mi][ni][3]);
            }
        }
        __syncthreads();   // both groups' gate buffers visible

        // pointwise: g = gate0 + gate1 + bias; thread owns col j = pj
        if (valid) {
#pragma unroll
            for (int qq = 0; qq < 2; qq++) {
                const int b   = pb0 + 32 * qq;
                const int col = col0 + pj;
                const uint32_t g0 = sb + SGATE + b * 272;
                const uint32_t g1 = g0 + GATEB;
                float gi = lds_f32(g0 + (0  + pj) * 4) + lds_f32(g1 + (0  + pj) * 4) + bi_;
                float gf = lds_f32(g0 + (16 + pj) * 4) + lds_f32(g1 + (16 + pj) * 4) + bf_;
                float gg = lds_f32(g0 + (32 + pj) * 4) + lds_f32(g1 + (32 + pj) * 4) + bg_;
                float go = lds_f32(g0 + (48 + pj) * 4) + lds_f32(g1 + (48 + pj) * 4) + bo_;
                const uint32_t caddr = sb + SCST + (b * 17 + pj) * 4;
                float c_old = lds_f32(caddr);
                float c_new = sigf(gf) * c_old + sigf(gi) * tanhf(gg);
                float h_new = sigf(go) * tanhf(c_new);
                sts_f32(caddr, c_new);
                if (u == 0) {
                    g_h0f[cur_wbuf][b][col] = __float2half(h_new);
                } else {
                    g_h1f[cur_wbuf][b][col] = __float2half(h_new);
                    g_Hout[((size_t)b * TT + tc) * HH + col] = h_new;
                }
            }
        }
        grid_barrier();
    }
}

// logits[m, v] = g_Hout[m, :] . Wout[v, :] + bout[v]  (M=32768, N=128, K=1024)
__global__ __launch_bounds__(128) void out_proj_kernel(
    const float* __restrict__ Wout, const float* __restrict__ bout,
    float* __restrict__ out)
{
    __shared__ float As[32][68];
    __shared__ float Ws[32][36];

    const int tid = threadIdx.x;
    const int m0  = blockIdx.x * 64;
    const int v0  = blockIdx.y * 32;
    const int tm  = tid & 15;
    const int tn  = tid >> 4;

    float acc[4][4];
#pragma unroll
    for (int i = 0; i < 4; i++)
#pragma unroll
        for (int j = 0; j < 4; j++) acc[i][j] = 0.0f;

#pragma unroll 1
    for (int k0 = 0; k0 < HH; k0 += 32) {
#pragma unroll
        for (int qy = 0; qy < 4; qy++) {
            int idx = tid + 128 * qy;
            int bb = idx >> 3, kv = idx & 7, k = k0 + kv * 4;
            float4 v = *reinterpret_cast<const float4*>(&g_Hout[(size_t)(m0 + bb) * HH + k]);
            int kr = kv * 4;
            As[kr + 0][bb] = v.x; As[kr + 1][bb] = v.y;
            As[kr + 2][bb] = v.z; As[kr + 3][bb] = v.w;
        }
#pragma unroll
        for (int qy = 0; qy < 2; qy++) {
            int idx = tid + 128 * qy;
            int n = idx >> 3, kv = idx & 7, k = k0 + kv * 4;
            float4 v = *reinterpret_cast<const float4*>(&Wout[(size_t)(v0 + n) * HH + k]);
            int kr = kv * 4;
            Ws[kr + 0][n] = v.x; Ws[kr + 1][n] = v.y;
            Ws[kr + 2][n] = v.z; Ws[kr + 3][n] = v.w;
        }
        __syncthreads();
#pragma unroll
        for (int kk = 0; kk < 32; kk++) {
            float4 a = *reinterpret_cast<const float4*>(&As[kk][tm << 2]);
            float4 w = *reinterpret_cast<const float4*>(&Ws[kk][tn << 2]);
            float av[4] = {a.x, a.y, a.z, a.w};
            float wv[4] = {w.x, w.y, w.z, w.w};
#pragma unroll
            for (int i = 0; i < 4; i++)
#pragma unroll
                for (int j = 0; j < 4; j++)
                    acc[i][j] = fmaf(av[i], wv[j], acc[i][j]);
        }
        __syncthreads();
    }

#pragma unroll
    for (int i = 0; i < 4; i++) {
        int m = m0 + (tm << 2) + i;
#pragma unroll
        for (int j = 0; j < 4; j++) {
            int v = v0 + (tn << 2) + j;
            out[(size_t)m * VV + v] = acc[i][j] + bout[v];
        }
    }
}

extern "C" void kernel_launch(void* const* d_in, const int* in_sizes, int n_in,
                              void* d_out, int out_size)
{
    const int*   x     = (const int*)d_in[0];
    const float* embed = (const float*)d_in[1];
    const float* Wx    = (const float*)d_in[2];
    const float* Wh    = (const float*)d_in[3];
    const float* bias  = (const float*)d_in[4];
    const float* Wout  = (const float*)d_in[5];
    const float* bout  = (const float*)d_in[6];
    float*       out   = (float*)d_out;

    static int smem_set = 0;
    if (!smem_set) {
        cudaFuncSetAttribute(lstm_persistent_kernel,
                             cudaFuncAttributeMaxDynamicSharedMemorySize, SMEM_DYN);
        smem_set = 1;
    }

    init_kernel<<<(2 * BB * HH + 255) / 256, 256>>>();
    convert_weights_kernel<<<(int)((2ull * 64 * 64 * 2048 + 255) / 256), 256>>>(Wx, Wh);
    convert_embed_kernel<<<(VV * DD + 255) / 256, 256>>>(embed);
    lstm_persistent_kernel<<<NCTA, NTHR, SMEM_DYN>>>(x, bias);
    out_proj_kernel<<<dim3(BB * TT / 64, VV / 32), 128>>>(Wout, bout, out);
}